// round 14
// baseline (speedup 1.0000x reference)
#include <cuda_runtime.h>
#include <cuda_fp16.h>
#include <cstdint>

#define BATCH 32
#define CH    256
#define HW    1024
#define EPSV  1e-5f
#define SCALE 0.0625f

// ---------------- scratch (device globals; no allocation allowed) ----------
__device__ __align__(256) __half  g_hxnt[(size_t)BATCH * HW * CH];  // [b][s][c]
__device__ __align__(256) __half  g_qh  [(size_t)BATCH * HW * CH];  // [b][s][c]
__device__ __align__(256) __half  g_kh  [(size_t)BATCH * HW * CH];  // [b][t][c]
__device__ __align__(256) __half  g_vh  [(size_t)BATCH * CH * HW];  // [b][c][t]
__device__ __align__(256) __half  g_attn[(size_t)BATCH * HW * HW];  // fp16 scores
__device__ __align__(256) __half  g_ph  [(size_t)BATCH * HW * HW];  // fp16 probs
__device__ __align__(256) __half  g_aoh [(size_t)BATCH * HW * CH];  // [b][s][c]
__device__ __align__(256) __half  g_wqh [3 * CH * CH];
__device__ __align__(256) __half  g_woh [CH * CH];

// ---------------- helpers ----------------------------------------------------
__device__ __forceinline__ uint32_t smem_u32(const void* p) {
    uint32_t a;
    asm("{ .reg .u64 t; cvta.to.shared.u64 t, %1; cvt.u32.u64 %0, t; }" : "=r"(a) : "l"(p));
    return a;
}

__device__ __forceinline__ void ldsm4(uint32_t* r, uint32_t addr) {
    asm volatile("ldmatrix.sync.aligned.m8n8.x4.shared.b16 {%0,%1,%2,%3}, [%4];"
        : "=r"(r[0]), "=r"(r[1]), "=r"(r[2]), "=r"(r[3]) : "r"(addr));
}

__device__ __forceinline__ void mma16816(float* c, const uint32_t* a, uint32_t b0, uint32_t b1) {
    asm volatile("mma.sync.aligned.m16n8k16.row.col.f32.f16.f16.f32 "
        "{%0,%1,%2,%3}, {%4,%5,%6,%7}, {%8,%9}, {%0,%1,%2,%3};"
        : "+f"(c[0]), "+f"(c[1]), "+f"(c[2]), "+f"(c[3])
        : "r"(a[0]), "r"(a[1]), "r"(a[2]), "r"(a[3]), "r"(b0), "r"(b1));
}

#define CP16(dst, src) \
    asm volatile("cp.async.cg.shared.global [%0], [%1], 16;" :: "r"(dst), "l"(src))
#define CPCOMMIT() asm volatile("cp.async.commit_group;" ::: "memory")
#define CPWAIT1()  asm volatile("cp.async.wait_group 1;"  ::: "memory")

__device__ __forceinline__ void st2(float* p, float x, float y) {
    float2 v; v.x = x; v.y = y; *(float2*)p = v;
}
__device__ __forceinline__ void sth2(__half* p, float x, float y) {
    *(__half2*)p = __floats2half2_rn(x, y);
}

// ---------------- unified HMMA GEMM (128x128 tile, warp 64x64, 128 thr) ------
// D[m][n] = sum_k A[m][k]*B[n][k], all operands plain fp16, fp32 accum.
// MODE 0: A=hxnt[s][c], B=wq[o][c]  K=256  -> q_h/k_h/v_h(transposed) + bias
// MODE 1: A=q_h[s][c],  B=k_h[t][c] K=256  -> attn[s][t]*SCALE (fp16)
// MODE 2: A=p_h[s][t],  B=v_h[c][t] K=1024 -> ao [s][c] fp16
// MODE 3: A=woh[o][c],  B=ao[s][c]  K=256  -> out[o][s] + bias + resid
#define KC     64                  // K per chunk
#define LDS    72                  // padded fp16 row stride (144B)
#define NT     128                 // block N
#define AELEM  (128 * LDS)         // 9216 halfs
#define OFF_BH (AELEM * 2)         // 18432 B
#define STAGEB ((AELEM + NT * LDS) * 2)   // 36864 B
#define SMEMB  (3 * STAGEB)               // 110592 B

template <int KTOT>
__device__ __forceinline__ void stage_chunk(
    const __half* __restrict__ Ap, const __half* __restrict__ Bp,
    uint32_t sbuf, int tid, int k0)
{
#pragma unroll
    for (int s = 0; s < 8; s++) {                       // A: 128 rows x 8 segs
        const int slot = tid + s * 128;
        const int row = slot >> 3, seg = slot & 7;
        CP16(sbuf + (uint32_t)((row * LDS + seg * 8) * 2),
             Ap + (size_t)row * KTOT + k0 + seg * 8);
    }
#pragma unroll
    for (int s = 0; s < 8; s++) {                       // B: 128 rows x 8 segs
        const int slot = tid + s * 128;
        const int row = slot >> 3, seg = slot & 7;
        CP16(sbuf + OFF_BH + (uint32_t)((row * LDS + seg * 8) * 2),
             Bp + (size_t)row * KTOT + k0 + seg * 8);
    }
}

template <int MODE>
__global__ void __launch_bounds__(128, 2) mma_gemm(
    const float* __restrict__ bias,
    const float* __restrict__ resid, float* __restrict__ Cout)
{
    constexpr int KTOT = (MODE == 2) ? 1024 : 256;
    constexpr int NCH = KTOT / KC;
    extern __shared__ __half dsm[];

    const int tid = threadIdx.x;
    const int lane = tid & 31, wid = tid >> 5;
    const int bz = blockIdx.z;
    const int bm = blockIdx.y * 128, bn = blockIdx.x * NT;

    const __half *Ah, *Bh;
    if (MODE == 0) { Ah = g_hxnt + (size_t)bz * HW * CH; Bh = g_wqh; }
    if (MODE == 1) { Ah = g_qh + (size_t)bz * HW * CH;   Bh = g_kh + (size_t)bz * HW * CH; }
    if (MODE == 2) { Ah = g_ph + (size_t)bz * HW * HW;   Bh = g_vh + (size_t)bz * CH * HW; }
    if (MODE == 3) { Ah = g_woh;                          Bh = g_aoh + (size_t)bz * HW * CH; }

    const __half* Ap = Ah + (size_t)bm * KTOT;
    const __half* Bp = Bh + (size_t)bn * KTOT;

    // 4 warps: 2m x 2n, warp tile 64x64
    const int wm = (wid >> 1) * 64, wn = (wid & 1) * 64;

    // ldmatrix base addresses relative to stage 0
    const uint32_t u0 = smem_u32(dsm);
    const int rowA = wm + (lane & 15);
    const int kOffA = (lane >> 4) << 3;
    const int rowB = wn + (lane & 7) + ((lane >> 4) << 3);
    const int kOffB = ((lane >> 3) & 1) << 3;
    uint32_t aHb[4], bHb[4];
#pragma unroll
    for (int mt = 0; mt < 4; mt++)
        aHb[mt] = u0 + (uint32_t)(((rowA + mt * 16) * LDS + kOffA) * 2);
#pragma unroll
    for (int p = 0; p < 4; p++)
        bHb[p] = u0 + (uint32_t)OFF_BH + (uint32_t)(((rowB + p * 16) * LDS + kOffB) * 2);

    float acc[4][8][4] = {};

    // prologue: issue chunks 0 and 1
    stage_chunk<KTOT>(Ap, Bp, u0, tid, 0);
    CPCOMMIT();
    stage_chunk<KTOT>(Ap, Bp, u0 + STAGEB, tid, KC);
    CPCOMMIT();

    for (int ch = 0; ch < NCH; ch++) {
        CPWAIT1();                 // chunk ch resident
        __syncthreads();
        if (ch + 2 < NCH) {
            const int nb = (ch + 2) % 3;
            stage_chunk<KTOT>(Ap, Bp, u0 + nb * STAGEB, tid, (ch + 2) * KC);
        }
        CPCOMMIT();                // uniform commit count

        const uint32_t boff = (uint32_t)((ch % 3) * STAGEB);
#pragma unroll
        for (int ks = 0; ks < 4; ks++) {
            uint32_t ahf[4][4];
#pragma unroll
            for (int mt = 0; mt < 4; mt++)
                ldsm4(ahf[mt], aHb[mt] + boff + ks * 32);
#pragma unroll
            for (int p = 0; p < 4; p++) {
                uint32_t bhf[4];
                ldsm4(bhf, bHb[p] + boff + ks * 32);
#pragma unroll
                for (int mt = 0; mt < 4; mt++)
#pragma unroll
                    for (int h = 0; h < 2; h++)
                        mma16816(acc[mt][p * 2 + h], ahf[mt], bhf[h * 2], bhf[h * 2 + 1]);
            }
        }
    }

    // ---------------- epilogue -----------------------------------------------
    const int gid = lane >> 2, qid = (lane & 3) * 2;

    if (MODE == 0) {
#pragma unroll
        for (int mt = 0; mt < 4; mt++) {
            const int s = bm + wm + mt * 16 + gid;
#pragma unroll
            for (int nt = 0; nt < 8; nt++) {
                const int oc = bn + wn + nt * 8 + qid;      // 0..767
                const int third = oc >> 8;
                const int cl = oc & 255;
                const float b0v = bias[oc], b1v = bias[oc + 1];
                float* a = acc[mt][nt];
                const float v0 = a[0] + b0v, v1 = a[1] + b1v;
                const float v2 = a[2] + b0v, v3 = a[3] + b1v;
                if (third == 0) {
                    sth2(&g_qh[((size_t)bz * HW + s) * CH + cl], v0, v1);
                    sth2(&g_qh[((size_t)bz * HW + s + 8) * CH + cl], v2, v3);
                } else if (third == 1) {
                    sth2(&g_kh[((size_t)bz * HW + s) * CH + cl], v0, v1);
                    sth2(&g_kh[((size_t)bz * HW + s + 8) * CH + cl], v2, v3);
                } else {
                    __half* vb = g_vh + (size_t)bz * CH * HW;
                    vb[(size_t)cl * HW + s]           = __float2half_rn(v0);
                    vb[(size_t)(cl + 1) * HW + s]     = __float2half_rn(v1);
                    vb[(size_t)cl * HW + s + 8]       = __float2half_rn(v2);
                    vb[(size_t)(cl + 1) * HW + s + 8] = __float2half_rn(v3);
                }
            }
        }
    }
    if (MODE == 1) {
        __half* dst = g_attn + (size_t)bz * HW * HW;
#pragma unroll
        for (int mt = 0; mt < 4; mt++) {
            const int s = bm + wm + mt * 16 + gid;
#pragma unroll
            for (int nt = 0; nt < 8; nt++) {
                const int t = bn + wn + nt * 8 + qid;
                float* a = acc[mt][nt];
                sth2(&dst[(size_t)s * HW + t], a[0] * SCALE, a[1] * SCALE);
                sth2(&dst[(size_t)(s + 8) * HW + t], a[2] * SCALE, a[3] * SCALE);
            }
        }
    }
    if (MODE == 2) {
#pragma unroll
        for (int mt = 0; mt < 4; mt++) {
            const int s = bm + wm + mt * 16 + gid;
#pragma unroll
            for (int nt = 0; nt < 8; nt++) {
                const int c = bn + wn + nt * 8 + qid;
                float* a = acc[mt][nt];
                sth2(&g_aoh[((size_t)bz * HW + s) * CH + c], a[0], a[1]);
                sth2(&g_aoh[((size_t)bz * HW + s + 8) * CH + c], a[2], a[3]);
            }
        }
    }
    if (MODE == 3) {
#pragma unroll
        for (int mt = 0; mt < 4; mt++) {
            const int o = bm + wm + mt * 16 + gid;
            const float bo0 = bias[o], bo8 = bias[o + 8];
#pragma unroll
            for (int nt = 0; nt < 8; nt++) {
                const int s = bn + wn + nt * 8 + qid;
                float* a = acc[mt][nt];
                size_t i0 = ((size_t)bz * CH + o) * HW + s;
                size_t i1 = ((size_t)bz * CH + o + 8) * HW + s;
                float2 rv0 = *(const float2*)&resid[i0];
                float2 rv1 = *(const float2*)&resid[i1];
                st2(&Cout[i0], a[0] + bo0 + rv0.x, a[1] + bo0 + rv0.y);
                st2(&Cout[i1], a[2] + bo8 + rv1.x, a[3] + bo8 + rv1.y);
            }
        }
    }
}

// ---------------- weight conversion ------------------------------------------
__global__ void convert_w(const float* __restrict__ wqkv, const float* __restrict__ wout)
{
    const int i = blockIdx.x * 256 + threadIdx.x;
    if (i < 3 * CH * CH)
        g_wqh[i] = __float2half_rn(wqkv[i]);
    if (i < CH * CH)
        g_woh[i] = __float2half_rn(wout[i]);
}

// ---------------- GroupNorm (smem-cached x; writes x_norm^T fp16) -------------
__global__ void gn_kernel(const float* __restrict__ x,
                          const float* __restrict__ wt,
                          const float* __restrict__ bs)
{
    extern __shared__ __half xc[];          // 32*1024 halfs = 64KB
    const int bg = blockIdx.x;              // b*8+g
    const int b = bg >> 3, g = bg & 7;
    const size_t base = (size_t)bg * (32 * HW);
    const int t = threadIdx.x;
    const float4* x4 = (const float4*)(x + base);

    float s = 0.f, s2 = 0.f;
#pragma unroll 4
    for (int i = t; i < 32 * HW / 4; i += 256) {
        float4 v = x4[i];
        s += v.x + v.y + v.z + v.w;
        s2 += v.x * v.x + v.y * v.y + v.z * v.z + v.w * v.w;
        __half2 h01 = __floats2half2_rn(v.x, v.y);
        __half2 h23 = __floats2half2_rn(v.z, v.w);
        uint2 pk; pk.x = *(uint32_t*)&h01; pk.y = *(uint32_t*)&h23;
        *(uint2*)(xc + i * 4) = pk;
    }
    __shared__ float rs[256], rq[256];
    rs[t] = s; rq[t] = s2;
    __syncthreads();
    for (int o = 128; o > 0; o >>= 1) {
        if (t < o) { rs[t] += rs[t + o]; rq[t] += rq[t + o]; }
        __syncthreads();
    }
    __shared__ float s_m, s_r;
    if (t == 0) {
        float m = rs[0] * (1.0f / (32.f * HW));
        float v = rq[0] * (1.0f / (32.f * HW)) - m * m;
        s_m = m; s_r = rsqrtf(v + EPSV);
    }
    __syncthreads();
    __shared__ float cw[32], cb[32];
    if (t < 32) {
        float w = wt[g * 32 + t] * s_r;
        cw[t] = w;
        cb[t] = bs[g * 32 + t] - s_m * w;
    }
    __syncthreads();

    __shared__ float sm[32][33];
    const int row = t >> 5, col = t & 31;
    for (int s0 = 0; s0 < HW; s0 += 32) {
#pragma unroll
        for (int cr = 0; cr < 32; cr += 8) {
            int c = cr + row;
            sm[c][col] = __half2float(xc[c * HW + s0 + col]) * cw[c] + cb[c];
        }
        __syncthreads();
#pragma unroll
        for (int sr = 0; sr < 32; sr += 8) {
            int sl = sr + row;
            g_hxnt[((size_t)b * HW + s0 + sl) * CH + g * 32 + col] =
                __float2half_rn(sm[col][sl]);
        }
        __syncthreads();
    }
}

// ---------------- softmax (fp16 scores -> fp16 probs) -------------------------
__global__ void softmax_kernel()
{
    const __half* row = g_attn + (size_t)blockIdx.x * HW;
    __half* orow = g_ph + (size_t)blockIdx.x * HW;
    const int t = threadIdx.x;
    uint2 raw = *(const uint2*)(row + t * 4);
    __half2 h01 = *(__half2*)&raw.x;
    __half2 h23 = *(__half2*)&raw.y;
    float vx = __half2float(h01.x), vy = __half2float(h01.y);
    float vz = __half2float(h23.x), vw = __half2float(h23.y);

    float m = fmaxf(fmaxf(vx, vy), fmaxf(vz, vw));
#pragma unroll
    for (int o = 16; o > 0; o >>= 1) m = fmaxf(m, __shfl_xor_sync(0xffffffffu, m, o));
    __shared__ float red[8];
    if ((t & 31) == 0) red[t >> 5] = m;
    __syncthreads();
    float mm = red[0];
#pragma unroll
    for (int i = 1; i < 8; i++) mm = fmaxf(mm, red[i]);
    __syncthreads();

    float e0 = __expf(vx - mm), e1 = __expf(vy - mm);
    float e2 = __expf(vz - mm), e3 = __expf(vw - mm);
    float s = e0 + e1 + e2 + e3;
#pragma unroll
    for (int o = 16; o > 0; o >>= 1) s += __shfl_xor_sync(0xffffffffu, s, o);
    if ((t & 31) == 0) red[t >> 5] = s;
    __syncthreads();
    float tot = 0.f;
#pragma unroll
    for (int i = 0; i < 8; i++) tot += red[i];
    float inv = 1.0f / tot;

    uint2 pk;
    __half2 p01 = __floats2half2_rn(e0 * inv, e1 * inv);
    __half2 p23 = __floats2half2_rn(e2 * inv, e3 * inv);
    pk.x = *(uint32_t*)&p01; pk.y = *(uint32_t*)&p23;
    *(uint2*)(orow + t * 4) = pk;
}

// ---------------- launch -------------------------------------------------------
extern "C" void kernel_launch(void* const* d_in, const int* in_sizes, int n_in,
                              void* d_out, int out_size)
{
    const float* x    = (const float*)d_in[0];
    const float* gnw  = (const float*)d_in[1];
    const float* gnb  = (const float*)d_in[2];
    const float* wqkv = (const float*)d_in[3];
    const float* bqkv = (const float*)d_in[4];
    const float* wout = (const float*)d_in[5];
    const float* bout = (const float*)d_in[6];
    float* out = (float*)d_out;

    const uint32_t smem_gemm = SMEMB;      // 110592
    const uint32_t smem_gn   = 65536;

    cudaFuncSetAttribute(mma_gemm<0>, cudaFuncAttributeMaxDynamicSharedMemorySize, smem_gemm);
    cudaFuncSetAttribute(mma_gemm<1>, cudaFuncAttributeMaxDynamicSharedMemorySize, smem_gemm);
    cudaFuncSetAttribute(mma_gemm<2>, cudaFuncAttributeMaxDynamicSharedMemorySize, smem_gemm);
    cudaFuncSetAttribute(mma_gemm<3>, cudaFuncAttributeMaxDynamicSharedMemorySize, smem_gemm);
    cudaFuncSetAttribute(gn_kernel, cudaFuncAttributeMaxDynamicSharedMemorySize, smem_gn);

    convert_w<<<(3 * CH * CH + 255) / 256, 256>>>(wqkv, wout);
    gn_kernel<<<BATCH * 8, 256, smem_gn>>>(x, gnw, gnb);
    // MODE0: M=1024 (s), N=768 (oc)
    mma_gemm<0><<<dim3(6, 8, BATCH), 128, smem_gemm>>>(bqkv, nullptr, nullptr);
    // MODE1: M=1024 (s), N=1024 (t)
    mma_gemm<1><<<dim3(8, 8, BATCH), 128, smem_gemm>>>(nullptr, nullptr, nullptr);
    softmax_kernel<<<BATCH * HW, 256>>>();
    // MODE2: M=1024 (s), N=256 (c), K=1024
    mma_gemm<2><<<dim3(2, 8, BATCH), 128, smem_gemm>>>(nullptr, nullptr, nullptr);
    // MODE3: M=256 (o), N=1024 (s)
    mma_gemm<3><<<dim3(8, 2, BATCH), 128, smem_gemm>>>(bout, x, out);
}

// round 15
// speedup vs baseline: 1.1749x; 1.1749x over previous
#include <cuda_runtime.h>
#include <cuda_fp16.h>
#include <cstdint>

#define BATCH 32
#define CH    256
#define HW    1024
#define EPSV  1e-5f
#define SCALE 0.0625f

// ---------------- scratch (device globals; no allocation allowed) ----------
__device__ __align__(256) __half  g_hxnt[(size_t)BATCH * HW * CH];  // [b][s][c]
__device__ __align__(256) __half  g_qh  [(size_t)BATCH * HW * CH];  // [b][s][c]
__device__ __align__(256) __half  g_kh  [(size_t)BATCH * HW * CH];  // [b][t][c]
__device__ __align__(256) __half  g_vh  [(size_t)BATCH * CH * HW];  // [b][c][t]
__device__ __align__(256) __half  g_attn[(size_t)BATCH * HW * HW];  // fp16 exp(scores)
__device__ __align__(256) float   g_rowsum[(size_t)BATCH * HW];     // fp32 row sums
__device__ __align__(256) __half  g_aoh [(size_t)BATCH * HW * CH];  // [b][s][c]
__device__ __align__(256) __half  g_wqh [3 * CH * CH];
__device__ __align__(256) __half  g_woh [CH * CH];

// ---------------- helpers ----------------------------------------------------
__device__ __forceinline__ uint32_t smem_u32(const void* p) {
    uint32_t a;
    asm("{ .reg .u64 t; cvta.to.shared.u64 t, %1; cvt.u32.u64 %0, t; }" : "=r"(a) : "l"(p));
    return a;
}

__device__ __forceinline__ void ldsm4(uint32_t* r, uint32_t addr) {
    asm volatile("ldmatrix.sync.aligned.m8n8.x4.shared.b16 {%0,%1,%2,%3}, [%4];"
        : "=r"(r[0]), "=r"(r[1]), "=r"(r[2]), "=r"(r[3]) : "r"(addr));
}

__device__ __forceinline__ void mma16816(float* c, const uint32_t* a, uint32_t b0, uint32_t b1) {
    asm volatile("mma.sync.aligned.m16n8k16.row.col.f32.f16.f16.f32 "
        "{%0,%1,%2,%3}, {%4,%5,%6,%7}, {%8,%9}, {%0,%1,%2,%3};"
        : "+f"(c[0]), "+f"(c[1]), "+f"(c[2]), "+f"(c[3])
        : "r"(a[0]), "r"(a[1]), "r"(a[2]), "r"(a[3]), "r"(b0), "r"(b1));
}

#define CP16(dst, src) \
    asm volatile("cp.async.cg.shared.global [%0], [%1], 16;" :: "r"(dst), "l"(src))
#define CPCOMMIT() asm volatile("cp.async.commit_group;" ::: "memory")
#define CPWAIT1()  asm volatile("cp.async.wait_group 1;"  ::: "memory")

__device__ __forceinline__ void st2(float* p, float x, float y) {
    float2 v; v.x = x; v.y = y; *(float2*)p = v;
}
__device__ __forceinline__ void sth2(__half* p, float x, float y) {
    *(__half2*)p = __floats2half2_rn(x, y);
}

// ---------------- unified HMMA GEMM (128xNT tile, K-chunk 64, 3-stage) -------
// D[m][n] = sum_k A[m][k]*B[n][k], all operands plain fp16, fp32 accum.
// MODE 0 (NT=64) : A=hxnt[s][c], B=wq[o][c]  -> q_h/k_h/v_h(transposed) + bias
// MODE 1 (NT=128): A=q_h[s][c],  B=k_h[t][c] -> attn[s][t]=exp(s*SCALE), rowsum +=
// MODE 2 (NT=128): A=attn[s][t], B=v_h[c][t] -> ao[s][c] = acc / rowsum[s]
// MODE 3 (NT=64) : A=woh[o][c],  B=ao[s][c]  -> out[o][s] + bias + resid
#define KC     64                  // K per chunk
#define LDS    72                  // padded fp16 row stride (144B)
#define AELEM  (128 * LDS)         // 9216 halfs
#define OFF_BH (AELEM * 2)         // 18432 B

template <int KTOT, int NT>
__device__ __forceinline__ void stage_chunk(
    const __half* __restrict__ Ap, const __half* __restrict__ Bp,
    uint32_t sbuf, int tid, int k0)
{
#pragma unroll
    for (int s = 0; s < 4; s++) {                       // A: 128 rows x 8 segs
        const int slot = tid + s * 256;
        const int row = slot >> 3, seg = slot & 7;
        CP16(sbuf + (uint32_t)((row * LDS + seg * 8) * 2),
             Ap + (size_t)row * KTOT + k0 + seg * 8);
    }
#pragma unroll
    for (int s = 0; s < NT / 32; s++) {                 // B: NT rows x 8 segs
        const int slot = tid + s * 256;
        const int row = slot >> 3, seg = slot & 7;
        CP16(sbuf + OFF_BH + (uint32_t)((row * LDS + seg * 8) * 2),
             Bp + (size_t)row * KTOT + k0 + seg * 8);
    }
}

template <int MODE, int NT>
__global__ void __launch_bounds__(256, 2) mma_gemm(
    const float* __restrict__ bias,
    const float* __restrict__ resid, float* __restrict__ Cout)
{
    constexpr int KTOT = (MODE == 2) ? 1024 : 256;
    constexpr int NCH = KTOT / KC;
    constexpr int NP = NT / 32;                          // B ldsm tiles per ks
    constexpr uint32_t STAGEB = (AELEM + NT * LDS) * 2;
    extern __shared__ __half dsm[];

    const int tid = threadIdx.x;
    const int lane = tid & 31, wid = tid >> 5;
    const int bz = blockIdx.z;
    const int bm = blockIdx.y * 128, bn = blockIdx.x * NT;

    const __half *Ah, *Bh;
    if (MODE == 0) { Ah = g_hxnt + (size_t)bz * HW * CH; Bh = g_wqh; }
    if (MODE == 1) { Ah = g_qh + (size_t)bz * HW * CH;   Bh = g_kh + (size_t)bz * HW * CH; }
    if (MODE == 2) { Ah = g_attn + (size_t)bz * HW * HW; Bh = g_vh + (size_t)bz * CH * HW; }
    if (MODE == 3) { Ah = g_woh;                          Bh = g_aoh + (size_t)bz * HW * CH; }

    const __half* Ap = Ah + (size_t)bm * KTOT;
    const __half* Bp = Bh + (size_t)bn * KTOT;

    const int wm = (wid >> 1) * 32, wn = (wid & 1) * (NT / 2);

    // ldmatrix base addresses relative to stage 0
    const uint32_t u0 = smem_u32(dsm);
    const int rowA = wm + (lane & 15);
    const int kOffA = (lane >> 4) << 3;
    const int rowB = wn + (lane & 7) + ((lane >> 4) << 3);
    const int kOffB = ((lane >> 3) & 1) << 3;
    uint32_t aHb[2], bHb[NP];
#pragma unroll
    for (int mt = 0; mt < 2; mt++)
        aHb[mt] = u0 + (uint32_t)(((rowA + mt * 16) * LDS + kOffA) * 2);
#pragma unroll
    for (int p = 0; p < NP; p++)
        bHb[p] = u0 + (uint32_t)OFF_BH + (uint32_t)(((rowB + p * 16) * LDS + kOffB) * 2);

    float acc[2][2 * NP][4] = {};

    // prologue: issue chunks 0 and 1
    stage_chunk<KTOT, NT>(Ap, Bp, u0, tid, 0);
    CPCOMMIT();
    stage_chunk<KTOT, NT>(Ap, Bp, u0 + STAGEB, tid, KC);
    CPCOMMIT();

    for (int ch = 0; ch < NCH; ch++) {
        CPWAIT1();                 // chunk ch resident
        __syncthreads();
        if (ch + 2 < NCH) {
            const int nb = (ch + 2) % 3;
            stage_chunk<KTOT, NT>(Ap, Bp, u0 + nb * STAGEB, tid, (ch + 2) * KC);
        }
        CPCOMMIT();                // uniform commit count

        const uint32_t boff = (uint32_t)((ch % 3) * STAGEB);
#pragma unroll
        for (int ks = 0; ks < 4; ks++) {
            uint32_t ahf[2][4];
#pragma unroll
            for (int mt = 0; mt < 2; mt++)
                ldsm4(ahf[mt], aHb[mt] + boff + ks * 32);
#pragma unroll
            for (int p = 0; p < NP; p++) {
                uint32_t bhf[4];
                ldsm4(bhf, bHb[p] + boff + ks * 32);
#pragma unroll
                for (int mt = 0; mt < 2; mt++)
#pragma unroll
                    for (int h = 0; h < 2; h++)
                        mma16816(acc[mt][p * 2 + h], ahf[mt], bhf[h * 2], bhf[h * 2 + 1]);
            }
        }
    }

    // ---------------- epilogue -----------------------------------------------
    const int gid = lane >> 2, qid = (lane & 3) * 2;

    if (MODE == 0) {
#pragma unroll
        for (int mt = 0; mt < 2; mt++) {
            const int s = bm + wm + mt * 16 + gid;
#pragma unroll
            for (int nt = 0; nt < 2 * NP; nt++) {
                const int oc = bn + wn + nt * 8 + qid;      // 0..767
                const int third = oc >> 8;
                const int cl = oc & 255;
                const float b0v = bias[oc], b1v = bias[oc + 1];
                float* a = acc[mt][nt];
                const float v0 = a[0] + b0v, v1 = a[1] + b1v;
                const float v2 = a[2] + b0v, v3 = a[3] + b1v;
                if (third == 0) {
                    sth2(&g_qh[((size_t)bz * HW + s) * CH + cl], v0, v1);
                    sth2(&g_qh[((size_t)bz * HW + s + 8) * CH + cl], v2, v3);
                } else if (third == 1) {
                    sth2(&g_kh[((size_t)bz * HW + s) * CH + cl], v0, v1);
                    sth2(&g_kh[((size_t)bz * HW + s + 8) * CH + cl], v2, v3);
                } else {
                    __half* vb = g_vh + (size_t)bz * CH * HW;
                    vb[(size_t)cl * HW + s]           = __float2half_rn(v0);
                    vb[(size_t)(cl + 1) * HW + s]     = __float2half_rn(v1);
                    vb[(size_t)cl * HW + s + 8]       = __float2half_rn(v2);
                    vb[(size_t)(cl + 1) * HW + s + 8] = __float2half_rn(v3);
                }
            }
        }
    }
    if (MODE == 1) {
        // store exp(score*SCALE) unnormalized; accumulate fp32 row sums
        __half* dst = g_attn + (size_t)bz * HW * HW;
        float* rsum = g_rowsum + (size_t)bz * HW;
#pragma unroll
        for (int mt = 0; mt < 2; mt++) {
            const int s = bm + wm + mt * 16 + gid;
            float r0 = 0.f, r1 = 0.f;
#pragma unroll
            for (int nt = 0; nt < 2 * NP; nt++) {
                const int t = bn + wn + nt * 8 + qid;
                float* a = acc[mt][nt];
                const float e0 = __expf(a[0] * SCALE), e1 = __expf(a[1] * SCALE);
                const float e2 = __expf(a[2] * SCALE), e3 = __expf(a[3] * SCALE);
                sth2(&dst[(size_t)s * HW + t], e0, e1);
                sth2(&dst[(size_t)(s + 8) * HW + t], e2, e3);
                r0 += e0 + e1;
                r1 += e2 + e3;
            }
            r0 += __shfl_xor_sync(0xffffffffu, r0, 1);
            r0 += __shfl_xor_sync(0xffffffffu, r0, 2);
            r1 += __shfl_xor_sync(0xffffffffu, r1, 1);
            r1 += __shfl_xor_sync(0xffffffffu, r1, 2);
            if ((lane & 3) == 0) {
                atomicAdd(&rsum[s], r0);
                atomicAdd(&rsum[s + 8], r1);
            }
        }
    }
    if (MODE == 2) {
        const float* rsum = g_rowsum + (size_t)bz * HW;
#pragma unroll
        for (int mt = 0; mt < 2; mt++) {
            const int s = bm + wm + mt * 16 + gid;
            const float inv0 = 1.0f / rsum[s];
            const float inv1 = 1.0f / rsum[s + 8];
#pragma unroll
            for (int nt = 0; nt < 2 * NP; nt++) {
                const int c = bn + wn + nt * 8 + qid;
                float* a = acc[mt][nt];
                sth2(&g_aoh[((size_t)bz * HW + s) * CH + c], a[0] * inv0, a[1] * inv0);
                sth2(&g_aoh[((size_t)bz * HW + s + 8) * CH + c], a[2] * inv1, a[3] * inv1);
            }
        }
    }
    if (MODE == 3) {
#pragma unroll
        for (int mt = 0; mt < 2; mt++) {
            const int o = bm + wm + mt * 16 + gid;
            const float bo0 = bias[o], bo8 = bias[o + 8];
#pragma unroll
            for (int nt = 0; nt < 2 * NP; nt++) {
                const int s = bn + wn + nt * 8 + qid;
                float* a = acc[mt][nt];
                size_t i0 = ((size_t)bz * CH + o) * HW + s;
                size_t i1 = ((size_t)bz * CH + o + 8) * HW + s;
                float2 rv0 = *(const float2*)&resid[i0];
                float2 rv1 = *(const float2*)&resid[i1];
                st2(&Cout[i0], a[0] + bo0 + rv0.x, a[1] + bo0 + rv0.y);
                st2(&Cout[i1], a[2] + bo8 + rv1.x, a[3] + bo8 + rv1.y);
            }
        }
    }
}

// ---------------- weight conversion + rowsum reset -----------------------------
__global__ void convert_w(const float* __restrict__ wqkv, const float* __restrict__ wout)
{
    const int i = blockIdx.x * 256 + threadIdx.x;
    if (i < 3 * CH * CH)
        g_wqh[i] = __float2half_rn(wqkv[i]);
    if (i < CH * CH)
        g_woh[i] = __float2half_rn(wout[i]);
    if (i < BATCH * HW)
        g_rowsum[i] = 0.0f;
}

// ---------------- GroupNorm (smem-cached x; writes x_norm^T fp16) -------------
__global__ void gn_kernel(const float* __restrict__ x,
                          const float* __restrict__ wt,
                          const float* __restrict__ bs)
{
    extern __shared__ __half xc[];          // 32*1024 halfs = 64KB
    const int bg = blockIdx.x;              // b*8+g
    const int b = bg >> 3, g = bg & 7;
    const size_t base = (size_t)bg * (32 * HW);
    const int t = threadIdx.x;
    const float4* x4 = (const float4*)(x + base);

    float s = 0.f, s2 = 0.f;
#pragma unroll 4
    for (int i = t; i < 32 * HW / 4; i += 256) {
        float4 v = x4[i];
        s += v.x + v.y + v.z + v.w;
        s2 += v.x * v.x + v.y * v.y + v.z * v.z + v.w * v.w;
        __half2 h01 = __floats2half2_rn(v.x, v.y);
        __half2 h23 = __floats2half2_rn(v.z, v.w);
        uint2 pk; pk.x = *(uint32_t*)&h01; pk.y = *(uint32_t*)&h23;
        *(uint2*)(xc + i * 4) = pk;
    }
    __shared__ float rs[256], rq[256];
    rs[t] = s; rq[t] = s2;
    __syncthreads();
    for (int o = 128; o > 0; o >>= 1) {
        if (t < o) { rs[t] += rs[t + o]; rq[t] += rq[t + o]; }
        __syncthreads();
    }
    __shared__ float s_m, s_r;
    if (t == 0) {
        float m = rs[0] * (1.0f / (32.f * HW));
        float v = rq[0] * (1.0f / (32.f * HW)) - m * m;
        s_m = m; s_r = rsqrtf(v + EPSV);
    }
    __syncthreads();
    __shared__ float cw[32], cb[32];
    if (t < 32) {
        float w = wt[g * 32 + t] * s_r;
        cw[t] = w;
        cb[t] = bs[g * 32 + t] - s_m * w;
    }
    __syncthreads();

    __shared__ float sm[32][33];
    const int row = t >> 5, col = t & 31;
    for (int s0 = 0; s0 < HW; s0 += 32) {
#pragma unroll
        for (int cr = 0; cr < 32; cr += 8) {
            int c = cr + row;
            sm[c][col] = __half2float(xc[c * HW + s0 + col]) * cw[c] + cb[c];
        }
        __syncthreads();
#pragma unroll
        for (int sr = 0; sr < 32; sr += 8) {
            int sl = sr + row;
            g_hxnt[((size_t)b * HW + s0 + sl) * CH + g * 32 + col] =
                __float2half_rn(sm[col][sl]);
        }
        __syncthreads();
    }
}

// ---------------- launch -------------------------------------------------------
extern "C" void kernel_launch(void* const* d_in, const int* in_sizes, int n_in,
                              void* d_out, int out_size)
{
    const float* x    = (const float*)d_in[0];
    const float* gnw  = (const float*)d_in[1];
    const float* gnb  = (const float*)d_in[2];
    const float* wqkv = (const float*)d_in[3];
    const float* bqkv = (const float*)d_in[4];
    const float* wout = (const float*)d_in[5];
    const float* bout = (const float*)d_in[6];
    float* out = (float*)d_out;

    // NT=64: 3*(9216+4608)*2 = 82944 ; NT=128: 3*(9216+9216)*2 = 110592
    const uint32_t smem_64  = 82944;
    const uint32_t smem_128 = 110592;
    const uint32_t smem_gn  = 65536;

    cudaFuncSetAttribute(mma_gemm<0,64>,  cudaFuncAttributeMaxDynamicSharedMemorySize, smem_64);
    cudaFuncSetAttribute(mma_gemm<1,128>, cudaFuncAttributeMaxDynamicSharedMemorySize, smem_128);
    cudaFuncSetAttribute(mma_gemm<2,128>, cudaFuncAttributeMaxDynamicSharedMemorySize, smem_128);
    cudaFuncSetAttribute(mma_gemm<3,64>,  cudaFuncAttributeMaxDynamicSharedMemorySize, smem_64);
    cudaFuncSetAttribute(gn_kernel, cudaFuncAttributeMaxDynamicSharedMemorySize, smem_gn);

    convert_w<<<(3 * CH * CH + 255) / 256, 256>>>(wqkv, wout);
    gn_kernel<<<BATCH * 8, 256, smem_gn>>>(x, gnw, gnb);
    mma_gemm<0,64><<<dim3(12, 8, BATCH), 256, smem_64>>>(bqkv, nullptr, nullptr);
    mma_gemm<1,128><<<dim3(8, 8, BATCH), 256, smem_128>>>(nullptr, nullptr, nullptr);
    mma_gemm<2,128><<<dim3(2, 8, BATCH), 256, smem_128>>>(nullptr, nullptr, nullptr);
    mma_gemm<3,64><<<dim3(16, 2, BATCH), 256, smem_64>>>(bout, x, out);
}

// round 16
// speedup vs baseline: 1.2207x; 1.0390x over previous
#include <cuda_runtime.h>
#include <cuda_fp16.h>
#include <cstdint>

#define BATCH 32
#define CH    256
#define HW    1024
#define EPSV  1e-5f
#define SCALE 0.0625f

// ---------------- scratch (device globals; no allocation allowed) ----------
__device__ __align__(256) __half  g_hxnt[(size_t)BATCH * HW * CH];  // [b][s][c]
__device__ __align__(256) __half  g_qh  [(size_t)BATCH * HW * CH];  // [b][s][c]
__device__ __align__(256) __half  g_kh  [(size_t)BATCH * HW * CH];  // [b][t][c]
__device__ __align__(256) __half  g_vh  [(size_t)BATCH * CH * HW];  // [b][c][t]
__device__ __align__(256) __half  g_attn[(size_t)BATCH * HW * HW];  // fp16 exp(scores)
__device__ __align__(256) float   g_rowsum[(size_t)BATCH * HW];     // fp32 row sums
__device__ __align__(256) __half  g_aoh [(size_t)BATCH * HW * CH];  // [b][s][c]
__device__ __align__(256) __half  g_wqh [3 * CH * CH];
__device__ __align__(256) __half  g_woh [CH * CH];

// ---------------- helpers ----------------------------------------------------
__device__ __forceinline__ uint32_t smem_u32(const void* p) {
    uint32_t a;
    asm("{ .reg .u64 t; cvta.to.shared.u64 t, %1; cvt.u32.u64 %0, t; }" : "=r"(a) : "l"(p));
    return a;
}

__device__ __forceinline__ void ldsm4(uint32_t* r, uint32_t addr) {
    asm volatile("ldmatrix.sync.aligned.m8n8.x4.shared.b16 {%0,%1,%2,%3}, [%4];"
        : "=r"(r[0]), "=r"(r[1]), "=r"(r[2]), "=r"(r[3]) : "r"(addr));
}

__device__ __forceinline__ void mma16816(float* c, const uint32_t* a, uint32_t b0, uint32_t b1) {
    asm volatile("mma.sync.aligned.m16n8k16.row.col.f32.f16.f16.f32 "
        "{%0,%1,%2,%3}, {%4,%5,%6,%7}, {%8,%9}, {%0,%1,%2,%3};"
        : "+f"(c[0]), "+f"(c[1]), "+f"(c[2]), "+f"(c[3])
        : "r"(a[0]), "r"(a[1]), "r"(a[2]), "r"(a[3]), "r"(b0), "r"(b1));
}

#define CP16(dst, src) \
    asm volatile("cp.async.cg.shared.global [%0], [%1], 16;" :: "r"(dst), "l"(src))
#define CPCOMMIT() asm volatile("cp.async.commit_group;" ::: "memory")
#define CPWAIT1()  asm volatile("cp.async.wait_group 1;"  ::: "memory")

__device__ __forceinline__ void st2(float* p, float x, float y) {
    float2 v; v.x = x; v.y = y; *(float2*)p = v;
}
__device__ __forceinline__ void sth2(__half* p, float x, float y) {
    *(__half2*)p = __floats2half2_rn(x, y);
}

// ---------------- unified HMMA GEMM (128x128 tile, K-chunk 64, 3-stage) ------
// D[m][n] = sum_k A[m][k]*B[n][k], all operands plain fp16, fp32 accum.
// MODE 0: A=hxnt[s][c], B=wq[o][c]  -> q_h/k_h/v_h(transposed) + bias
// MODE 1: A=q_h[s][c],  B=k_h[t][c] -> attn[s][t]=exp(s*SCALE), rowsum +=
// MODE 2: A=attn[s][t], B=v_h[c][t] -> ao[s][c] = acc / rowsum[s]
// MODE 3: A=woh[o][c],  B=ao[s][c]  -> out[o][s] + bias + resid
#define KC     64                  // K per chunk
#define LDS    72                  // padded fp16 row stride (144B)
#define NT     128                 // block N
#define AELEM  (128 * LDS)         // 9216 halfs
#define OFF_BH (AELEM * 2)         // 18432 B
#define STAGEB ((AELEM + NT * LDS) * 2)   // 36864 B
#define SMEMB  (3 * STAGEB)               // 110592 B

template <int KTOT>
__device__ __forceinline__ void stage_chunk(
    const __half* __restrict__ Ap, const __half* __restrict__ Bp,
    uint32_t sbuf, int tid, int k0)
{
#pragma unroll
    for (int s = 0; s < 4; s++) {                       // A: 128 rows x 8 segs
        const int slot = tid + s * 256;
        const int row = slot >> 3, seg = slot & 7;
        CP16(sbuf + (uint32_t)((row * LDS + seg * 8) * 2),
             Ap + (size_t)row * KTOT + k0 + seg * 8);
    }
#pragma unroll
    for (int s = 0; s < 4; s++) {                       // B: 128 rows x 8 segs
        const int slot = tid + s * 256;
        const int row = slot >> 3, seg = slot & 7;
        CP16(sbuf + OFF_BH + (uint32_t)((row * LDS + seg * 8) * 2),
             Bp + (size_t)row * KTOT + k0 + seg * 8);
    }
}

template <int MODE>
__global__ void __launch_bounds__(256, 2) mma_gemm(
    const float* __restrict__ bias,
    const float* __restrict__ resid, float* __restrict__ Cout)
{
    constexpr int KTOT = (MODE == 2) ? 1024 : 256;
    constexpr int NCH = KTOT / KC;
    extern __shared__ __half dsm[];

    const int tid = threadIdx.x;
    const int lane = tid & 31, wid = tid >> 5;
    const int bz = blockIdx.z;
    const int bm = blockIdx.y * 128, bn = blockIdx.x * NT;

    const __half *Ah, *Bh;
    if (MODE == 0) { Ah = g_hxnt + (size_t)bz * HW * CH; Bh = g_wqh; }
    if (MODE == 1) { Ah = g_qh + (size_t)bz * HW * CH;   Bh = g_kh + (size_t)bz * HW * CH; }
    if (MODE == 2) { Ah = g_attn + (size_t)bz * HW * HW; Bh = g_vh + (size_t)bz * CH * HW; }
    if (MODE == 3) { Ah = g_woh;                          Bh = g_aoh + (size_t)bz * HW * CH; }

    const __half* Ap = Ah + (size_t)bm * KTOT;
    const __half* Bp = Bh + (size_t)bn * KTOT;

    const int wm = (wid >> 1) * 32, wn = (wid & 1) * 64;

    // ldmatrix base addresses relative to stage 0
    const uint32_t u0 = smem_u32(dsm);
    const int rowA = wm + (lane & 15);
    const int kOffA = (lane >> 4) << 3;
    const int rowB = wn + (lane & 7) + ((lane >> 4) << 3);
    const int kOffB = ((lane >> 3) & 1) << 3;
    uint32_t aHb[2], bHb[4];
#pragma unroll
    for (int mt = 0; mt < 2; mt++)
        aHb[mt] = u0 + (uint32_t)(((rowA + mt * 16) * LDS + kOffA) * 2);
#pragma unroll
    for (int p = 0; p < 4; p++)
        bHb[p] = u0 + (uint32_t)OFF_BH + (uint32_t)(((rowB + p * 16) * LDS + kOffB) * 2);

    float acc[2][8][4] = {};

    // prologue: issue chunks 0 and 1
    stage_chunk<KTOT>(Ap, Bp, u0, tid, 0);
    CPCOMMIT();
    stage_chunk<KTOT>(Ap, Bp, u0 + STAGEB, tid, KC);
    CPCOMMIT();

    for (int ch = 0; ch < NCH; ch++) {
        CPWAIT1();                 // chunk ch resident
        __syncthreads();
        if (ch + 2 < NCH) {
            const int nb = (ch + 2) % 3;
            stage_chunk<KTOT>(Ap, Bp, u0 + nb * STAGEB, tid, (ch + 2) * KC);
        }
        CPCOMMIT();                // uniform commit count

        const uint32_t boff = (uint32_t)((ch % 3) * STAGEB);
#pragma unroll
        for (int ks = 0; ks < 4; ks++) {
            uint32_t ahf[2][4];
#pragma unroll
            for (int mt = 0; mt < 2; mt++)
                ldsm4(ahf[mt], aHb[mt] + boff + ks * 32);
#pragma unroll
            for (int p = 0; p < 4; p++) {
                uint32_t bhf[4];
                ldsm4(bhf, bHb[p] + boff + ks * 32);
#pragma unroll
                for (int mt = 0; mt < 2; mt++)
#pragma unroll
                    for (int h = 0; h < 2; h++)
                        mma16816(acc[mt][p * 2 + h], ahf[mt], bhf[h * 2], bhf[h * 2 + 1]);
            }
        }
    }

    // ---------------- epilogue -----------------------------------------------
    const int gid = lane >> 2, qid = (lane & 3) * 2;

    if (MODE == 0) {
#pragma unroll
        for (int mt = 0; mt < 2; mt++) {
            const int s = bm + wm + mt * 16 + gid;
#pragma unroll
            for (int nt = 0; nt < 8; nt++) {
                const int oc = bn + wn + nt * 8 + qid;      // 0..767
                const int third = oc >> 8;
                const int cl = oc & 255;
                const float b0v = bias[oc], b1v = bias[oc + 1];
                float* a = acc[mt][nt];
                const float v0 = a[0] + b0v, v1 = a[1] + b1v;
                const float v2 = a[2] + b0v, v3 = a[3] + b1v;
                if (third == 0) {
                    sth2(&g_qh[((size_t)bz * HW + s) * CH + cl], v0, v1);
                    sth2(&g_qh[((size_t)bz * HW + s + 8) * CH + cl], v2, v3);
                } else if (third == 1) {
                    sth2(&g_kh[((size_t)bz * HW + s) * CH + cl], v0, v1);
                    sth2(&g_kh[((size_t)bz * HW + s + 8) * CH + cl], v2, v3);
                } else {
                    __half* vb = g_vh + (size_t)bz * CH * HW;
                    vb[(size_t)cl * HW + s]           = __float2half_rn(v0);
                    vb[(size_t)(cl + 1) * HW + s]     = __float2half_rn(v1);
                    vb[(size_t)cl * HW + s + 8]       = __float2half_rn(v2);
                    vb[(size_t)(cl + 1) * HW + s + 8] = __float2half_rn(v3);
                }
            }
        }
    }
    if (MODE == 1) {
        // store exp(score*SCALE) unnormalized; accumulate fp32 row sums
        __half* dst = g_attn + (size_t)bz * HW * HW;
        float* rsum = g_rowsum + (size_t)bz * HW;
#pragma unroll
        for (int mt = 0; mt < 2; mt++) {
            const int s = bm + wm + mt * 16 + gid;
            float r0 = 0.f, r1 = 0.f;
#pragma unroll
            for (int nt = 0; nt < 8; nt++) {
                const int t = bn + wn + nt * 8 + qid;
                float* a = acc[mt][nt];
                const float e0 = __expf(a[0] * SCALE), e1 = __expf(a[1] * SCALE);
                const float e2 = __expf(a[2] * SCALE), e3 = __expf(a[3] * SCALE);
                sth2(&dst[(size_t)s * HW + t], e0, e1);
                sth2(&dst[(size_t)(s + 8) * HW + t], e2, e3);
                r0 += e0 + e1;
                r1 += e2 + e3;
            }
            r0 += __shfl_xor_sync(0xffffffffu, r0, 1);
            r0 += __shfl_xor_sync(0xffffffffu, r0, 2);
            r1 += __shfl_xor_sync(0xffffffffu, r1, 1);
            r1 += __shfl_xor_sync(0xffffffffu, r1, 2);
            if ((lane & 3) == 0) {
                atomicAdd(&rsum[s], r0);
                atomicAdd(&rsum[s + 8], r1);
            }
        }
    }
    if (MODE == 2) {
        const float* rsum = g_rowsum + (size_t)bz * HW;
#pragma unroll
        for (int mt = 0; mt < 2; mt++) {
            const int s = bm + wm + mt * 16 + gid;
            const float inv0 = 1.0f / rsum[s];
            const float inv1 = 1.0f / rsum[s + 8];
#pragma unroll
            for (int nt = 0; nt < 8; nt++) {
                const int c = bn + wn + nt * 8 + qid;
                float* a = acc[mt][nt];
                sth2(&g_aoh[((size_t)bz * HW + s) * CH + c], a[0] * inv0, a[1] * inv0);
                sth2(&g_aoh[((size_t)bz * HW + s + 8) * CH + c], a[2] * inv1, a[3] * inv1);
            }
        }
    }
    if (MODE == 3) {
#pragma unroll
        for (int mt = 0; mt < 2; mt++) {
            const int o = bm + wm + mt * 16 + gid;
            const float bo0 = bias[o], bo8 = bias[o + 8];
#pragma unroll
            for (int nt = 0; nt < 8; nt++) {
                const int s = bn + wn + nt * 8 + qid;
                float* a = acc[mt][nt];
                size_t i0 = ((size_t)bz * CH + o) * HW + s;
                size_t i1 = ((size_t)bz * CH + o + 8) * HW + s;
                float2 rv0 = *(const float2*)&resid[i0];
                float2 rv1 = *(const float2*)&resid[i1];
                st2(&Cout[i0], a[0] + bo0 + rv0.x, a[1] + bo0 + rv0.y);
                st2(&Cout[i1], a[2] + bo8 + rv1.x, a[3] + bo8 + rv1.y);
            }
        }
    }
}

// ---------------- GroupNorm (+ fused weight convert + rowsum reset) -----------
__global__ void gn_kernel(const float* __restrict__ x,
                          const float* __restrict__ wt,
                          const float* __restrict__ bs,
                          const float* __restrict__ wqkv,
                          const float* __restrict__ wout)
{
    extern __shared__ __half xc[];          // 32*1024 halfs = 64KB
    const int bg = blockIdx.x;              // b*8+g
    const int b = bg >> 3, g = bg & 7;
    const size_t base = (size_t)bg * (32 * HW);
    const int t = threadIdx.x;
    const int gtid = bg * 256 + t;          // 0..65535

    // fused one-time conversions (grid-stride over 65536 threads)
#pragma unroll
    for (int r = 0; r < 3; r++) {
        const int i = gtid + r * 65536;     // covers 196608 = 3*CH*CH
        g_wqh[i] = __float2half_rn(wqkv[i]);
    }
    if (gtid < CH * CH)
        g_woh[gtid] = __float2half_rn(wout[gtid]);
    if (gtid < BATCH * HW)
        g_rowsum[gtid] = 0.0f;

    const float4* x4 = (const float4*)(x + base);
    float s = 0.f, s2 = 0.f;
#pragma unroll 4
    for (int i = t; i < 32 * HW / 4; i += 256) {
        float4 v = x4[i];
        s += v.x + v.y + v.z + v.w;
        s2 += v.x * v.x + v.y * v.y + v.z * v.z + v.w * v.w;
        __half2 h01 = __floats2half2_rn(v.x, v.y);
        __half2 h23 = __floats2half2_rn(v.z, v.w);
        uint2 pk; pk.x = *(uint32_t*)&h01; pk.y = *(uint32_t*)&h23;
        *(uint2*)(xc + i * 4) = pk;
    }
    __shared__ float rs[256], rq[256];
    rs[t] = s; rq[t] = s2;
    __syncthreads();
    for (int o = 128; o > 0; o >>= 1) {
        if (t < o) { rs[t] += rs[t + o]; rq[t] += rq[t + o]; }
        __syncthreads();
    }
    __shared__ float s_m, s_r;
    if (t == 0) {
        float m = rs[0] * (1.0f / (32.f * HW));
        float v = rq[0] * (1.0f / (32.f * HW)) - m * m;
        s_m = m; s_r = rsqrtf(v + EPSV);
    }
    __syncthreads();
    __shared__ float cw[32], cb[32];
    if (t < 32) {
        float w = wt[g * 32 + t] * s_r;
        cw[t] = w;
        cb[t] = bs[g * 32 + t] - s_m * w;
    }
    __syncthreads();

    __shared__ float sm[32][33];
    const int row = t >> 5, col = t & 31;
    for (int s0 = 0; s0 < HW; s0 += 32) {
#pragma unroll
        for (int cr = 0; cr < 32; cr += 8) {
            int c = cr + row;
            sm[c][col] = __half2float(xc[c * HW + s0 + col]) * cw[c] + cb[c];
        }
        __syncthreads();
#pragma unroll
        for (int sr = 0; sr < 32; sr += 8) {
            int sl = sr + row;
            g_hxnt[((size_t)b * HW + s0 + sl) * CH + g * 32 + col] =
                __float2half_rn(sm[col][sl]);
        }
        __syncthreads();
    }
}

// ---------------- launch -------------------------------------------------------
extern "C" void kernel_launch(void* const* d_in, const int* in_sizes, int n_in,
                              void* d_out, int out_size)
{
    const float* x    = (const float*)d_in[0];
    const float* gnw  = (const float*)d_in[1];
    const float* gnb  = (const float*)d_in[2];
    const float* wqkv = (const float*)d_in[3];
    const float* bqkv = (const float*)d_in[4];
    const float* wout = (const float*)d_in[5];
    const float* bout = (const float*)d_in[6];
    float* out = (float*)d_out;

    const uint32_t smem_gemm = SMEMB;      // 110592
    const uint32_t smem_gn   = 65536;

    cudaFuncSetAttribute(mma_gemm<0>, cudaFuncAttributeMaxDynamicSharedMemorySize, smem_gemm);
    cudaFuncSetAttribute(mma_gemm<1>, cudaFuncAttributeMaxDynamicSharedMemorySize, smem_gemm);
    cudaFuncSetAttribute(mma_gemm<2>, cudaFuncAttributeMaxDynamicSharedMemorySize, smem_gemm);
    cudaFuncSetAttribute(mma_gemm<3>, cudaFuncAttributeMaxDynamicSharedMemorySize, smem_gemm);
    cudaFuncSetAttribute(gn_kernel, cudaFuncAttributeMaxDynamicSharedMemorySize, smem_gn);

    gn_kernel<<<BATCH * 8, 256, smem_gn>>>(x, gnw, gnb, wqkv, wout);
    // MODE0: M=1024 (s), N=768 (oc)
    mma_gemm<0><<<dim3(6, 8, BATCH), 256, smem_gemm>>>(bqkv, nullptr, nullptr);
    // MODE1: M=1024 (s), N=1024 (t)
    mma_gemm<1><<<dim3(8, 8, BATCH), 256, smem_gemm>>>(nullptr, nullptr, nullptr);
    // MODE2: M=1024 (s), N=256 (c), K=1024
    mma_gemm<2><<<dim3(2, 8, BATCH), 256, smem_gemm>>>(nullptr, nullptr, nullptr);
    // MODE3: M=256 (o), N=1024 (s)
    mma_gemm<3><<<dim3(8, 2, BATCH), 256, smem_gemm>>>(bout, x, out);
}